// round 7
// baseline (speedup 1.0000x reference)
#include <cuda_runtime.h>
#include <cstdint>

#define COLS 8192
#define COLS4 2048
#define ROWS 1024
#define SCALE 0.75f
#define GRID 148
#define NSTAGES 6
#define ROW_BYTES (COLS * 4)          // 32 KB per stage
#define MAXK 7                        // ceil(1024/148)
#define DYN_SMEM (1024 + NSTAGES * ROW_BYTES)   // 197,632 B

// Scratch (no allocation allowed).
__device__ __align__(32) float g_wtotal[COLS];

// ---------------- mbarrier / TMA helpers ----------------
__device__ __forceinline__ uint32_t smem_u32(const void* p) {
    return (uint32_t)__cvta_generic_to_shared(p);
}
__device__ __forceinline__ void mbar_init(uint32_t mbar, uint32_t count) {
    asm volatile("mbarrier.init.shared.b64 [%0], %1;" :: "r"(mbar), "r"(count) : "memory");
}
__device__ __forceinline__ void mbar_expect_tx(uint32_t mbar, uint32_t bytes) {
    asm volatile("mbarrier.arrive.expect_tx.shared.b64 _, [%0], %1;"
                 :: "r"(mbar), "r"(bytes) : "memory");
}
__device__ __forceinline__ void mbar_arrive(uint32_t mbar) {
    asm volatile("mbarrier.arrive.shared.b64 _, [%0];" :: "r"(mbar) : "memory");
}
// Acquire wait (consumers: generic LDS after this).
__device__ __forceinline__ void mbar_wait_acq(uint32_t mbar, uint32_t parity) {
    asm volatile(
        "{\n\t.reg .pred P;\n\t"
        "W_%=:\n\t"
        "mbarrier.try_wait.parity.acquire.cta.shared::cta.b64 P, [%0], %1, 0x989680;\n\t"
        "@P bra.uni D_%=;\n\t"
        "bra.uni W_%=;\n\t"
        "D_%=:\n\t}"
        :: "r"(mbar), "r"(parity) : "memory");
}
// Relaxed wait (producer: post-wait access is async-proxy TMA only).
__device__ __forceinline__ void mbar_wait_rlx(uint32_t mbar, uint32_t parity) {
    asm volatile(
        "{\n\t.reg .pred P;\n\t"
        "W_%=:\n\t"
        "mbarrier.try_wait.parity.relaxed.cta.shared::cta.b64 P, [%0], %1, 0x989680;\n\t"
        "@P bra.uni D_%=;\n\t"
        "bra.uni W_%=;\n\t"
        "D_%=:\n\t}"
        :: "r"(mbar), "r"(parity) : "memory");
}
// 1D bulk copy gmem -> smem with mbarrier completion.
__device__ __forceinline__ void tma_bulk_1d(uint32_t dst, const float* src,
                                            uint32_t bytes, uint32_t mbar) {
    asm volatile(
        "cp.async.bulk.shared::cta.global.mbarrier::complete_tx::bytes [%0], [%1], %2, [%3];"
        :: "r"(dst), "l"(src), "r"(bytes), "r"(mbar) : "memory");
}

// ---------------- Kernel 1: w_total[c] = sum_g wsums[g][c] ----------------
__global__ __launch_bounds__(256) void reduce_w_kernel(const float* __restrict__ wsums) {
    const int lcol  = threadIdx.x & 31;
    const int chunk = threadIdx.x >> 5;               // 0..7, 4 groups each
    const int c4    = blockIdx.x * 32 + lcol;

    const float4* __restrict__ w4 = reinterpret_cast<const float4*>(wsums);
    float4 s = make_float4(0.f, 0.f, 0.f, 0.f);
#pragma unroll
    for (int g = 0; g < 4; ++g) {
        float4 v = w4[(size_t)(chunk * 4 + g) * COLS4 + c4];
        s.x += v.x; s.y += v.y; s.z += v.z; s.w += v.w;
    }

    __shared__ float4 sm[8][32];
    sm[chunk][lcol] = s;
    __syncthreads();

    if (threadIdx.x < 32) {
        float4 r = make_float4(0.f, 0.f, 0.f, 0.f);
#pragma unroll
        for (int c = 0; c < 8; ++c) {
            float4 v = sm[c][threadIdx.x];
            r.x += v.x; r.y += v.y; r.z += v.z; r.w += v.w;
        }
        reinterpret_cast<float4*>(g_wtotal)[c4] = r;
    }
}

// ---------------- Kernel 2: persistent TMA-pipelined matvec ----------------
// Grid 148, 1 block/SM, 256 threads. Block b handles rows b, b+148, ...
// Producer (tid 0) keeps a 6-deep ring of 32KB row copies in flight via
// cp.async.bulk; consumers (all 256 threads) dot each arriving row against
// a register-resident w chunk. All reductions deferred to the end.
__global__ __launch_bounds__(256, 1) void dot_tma_kernel(const float* __restrict__ x,
                                                         float* __restrict__ out) {
    extern __shared__ __align__(128) unsigned char dsm[];
    const int t   = threadIdx.x;
    const int bid = blockIdx.x;

    const uint32_t smb = smem_u32(dsm);
    // barriers: full[s] = smb + s*16, empty[s] = smb + s*16 + 8; stages at +1024
    const uint32_t stage0 = smb + 1024;

    if (t == 0) {
#pragma unroll
        for (int s = 0; s < NSTAGES; ++s) {
            mbar_init(smb + s * 16, 1);        // full: expect_tx arrive
            mbar_init(smb + s * 16 + 8, 256);  // empty: all threads arrive
        }
        asm volatile("fence.proxy.async.shared::cta;" ::: "memory");
    }
    __syncthreads();

    // w chunk in registers: thread t owns float4s {j*256+t}, j=0..7.
    float4 w[8];
    const float4* __restrict__ w4 = reinterpret_cast<const float4*>(g_wtotal);
#pragma unroll
    for (int j = 0; j < 8; ++j) w[j] = w4[j * 256 + t];

    const int nrows = (ROWS - 1 - bid) / GRID + 1;   // 6 or 7

    // Producer state (meaningful in tid 0 only).
    int pstage = 0, pphase = 1, pi = 0;
    if (t == 0) {
        const int prefill = nrows < NSTAGES ? nrows : NSTAGES;
        for (; pi < prefill; ++pi) {
            mbar_wait_rlx(smb + pstage * 16 + 8, pphase);   // passes immediately (fresh barriers)
            mbar_expect_tx(smb + pstage * 16, ROW_BYTES);
            tma_bulk_1d(stage0 + pstage * ROW_BYTES,
                        x + (size_t)(bid + pi * GRID) * COLS, ROW_BYTES,
                        smb + pstage * 16);
            if (++pstage == NSTAGES) { pstage = 0; pphase ^= 1; }
        }
    }

    float s[MAXK];
    int cstage = 0, cphase = 0;
    for (int k = 0; k < nrows; ++k) {
        mbar_wait_acq(smb + cstage * 16, cphase);

        const float4* xs = reinterpret_cast<const float4*>(dsm + 1024 + cstage * ROW_BYTES);
        float4 a[8];
#pragma unroll
        for (int j = 0; j < 8; ++j) a[j] = xs[j * 256 + t];

        float p0 = 0.f, p1 = 0.f;
#pragma unroll
        for (int j = 0; j < 8; j += 2) {
            p0 = fmaf(a[j].x,     w[j].x,     p0);
            p0 = fmaf(a[j].y,     w[j].y,     p0);
            p0 = fmaf(a[j].z,     w[j].z,     p0);
            p0 = fmaf(a[j].w,     w[j].w,     p0);
            p1 = fmaf(a[j + 1].x, w[j + 1].x, p1);
            p1 = fmaf(a[j + 1].y, w[j + 1].y, p1);
            p1 = fmaf(a[j + 1].z, w[j + 1].z, p1);
            p1 = fmaf(a[j + 1].w, w[j + 1].w, p1);
        }
        s[k] = p0 + p1;

        mbar_arrive(smb + cstage * 16 + 8);
        if (++cstage == NSTAGES) { cstage = 0; cphase ^= 1; }

        // Producer refill: the stage just freed is exactly pstage.
        if (t == 0 && pi < nrows) {
            mbar_wait_rlx(smb + pstage * 16 + 8, pphase);
            mbar_expect_tx(smb + pstage * 16, ROW_BYTES);
            tma_bulk_1d(stage0 + pstage * ROW_BYTES,
                        x + (size_t)(bid + pi * GRID) * COLS, ROW_BYTES,
                        smb + pstage * 16);
            ++pi;
            if (++pstage == NSTAGES) { pstage = 0; pphase ^= 1; }
        }
    }

    // Deferred block reductions for all rows at once.
#pragma unroll
    for (int o = 16; o > 0; o >>= 1) {
#pragma unroll
        for (int k = 0; k < MAXK; ++k)
            if (k < nrows) s[k] += __shfl_xor_sync(0xFFFFFFFFu, s[k], o);
    }

    __shared__ float red[MAXK][8];
    const int wid = t >> 5, lid = t & 31;
    if (lid == 0) {
#pragma unroll
        for (int k = 0; k < MAXK; ++k)
            if (k < nrows) red[k][wid] = s[k];
    }
    __syncthreads();

    if (t < nrows) {
        float v = 0.f;
#pragma unroll
        for (int w8 = 0; w8 < 8; ++w8) v += red[t][w8];
        out[bid + t * GRID] = v * SCALE;
    }
}

extern "C" void kernel_launch(void* const* d_in, const int* in_sizes, int n_in,
                              void* d_out, int out_size) {
    const float* x     = (const float*)d_in[0];  // [1024, 8192] f32
    const float* wsums = (const float*)d_in[1];  // [32, 8192] f32
    float* out         = (float*)d_out;          // [1024, 1] f32

    cudaFuncSetAttribute(dot_tma_kernel,
                         cudaFuncAttributeMaxDynamicSharedMemorySize, DYN_SMEM);

    reduce_w_kernel<<<COLS4 / 32, 256>>>(wsums);
    dot_tma_kernel<<<GRID, 256, DYN_SMEM>>>(x, out);
}

// round 8
// speedup vs baseline: 1.0239x; 1.0239x over previous
#include <cuda_runtime.h>
#include <cstdint>

#define COLS 8192
#define COLS4 2048
#define ROWS 1024
#define SCALE 0.75f
#define GRID 148
#define NTHR 512
#define NST 6
#define STAGE_BYTES (COLS * 4)                  // 32 KB
#define DYN_SMEM (NST * STAGE_BYTES)            // 196608 B
#define MAXK 7                                  // ceil(1024/148)

// Scratch (no allocation allowed).
__device__ __align__(32) float g_wtotal[COLS];

__device__ __forceinline__ void cp16(uint32_t dst, const float* src) {
    asm volatile("cp.async.cg.shared.global [%0], [%1], 16;"
                 :: "r"(dst), "l"(src) : "memory");
}
#define CP_COMMIT() asm volatile("cp.async.commit_group;" ::: "memory")
#define CP_WAIT(n)  asm volatile("cp.async.wait_group %0;" :: "n"(n) : "memory")

// ---------------- Kernel 1: w_total[c] = sum_g wsums[g][c] ----------------
__global__ __launch_bounds__(256) void reduce_w_kernel(const float* __restrict__ wsums) {
    const int lcol  = threadIdx.x & 31;
    const int chunk = threadIdx.x >> 5;               // 0..7, 4 groups each
    const int c4    = blockIdx.x * 32 + lcol;

    const float4* __restrict__ w4 = reinterpret_cast<const float4*>(wsums);
    float4 s = make_float4(0.f, 0.f, 0.f, 0.f);
#pragma unroll
    for (int g = 0; g < 4; ++g) {
        float4 v = w4[(size_t)(chunk * 4 + g) * COLS4 + c4];
        s.x += v.x; s.y += v.y; s.z += v.z; s.w += v.w;
    }

    __shared__ float4 sm[8][32];
    sm[chunk][lcol] = s;
    __syncthreads();

    if (threadIdx.x < 32) {
        float4 r = make_float4(0.f, 0.f, 0.f, 0.f);
#pragma unroll
        for (int c = 0; c < 8; ++c) {
            float4 v = sm[c][threadIdx.x];
            r.x += v.x; r.y += v.y; r.z += v.z; r.w += v.w;
        }
        reinterpret_cast<float4*>(g_wtotal)[c4] = r;
    }
}

// ---------------- Kernel 2: per-thread cp.async pipelined matvec ----------------
// Grid 148 x 512 threads, persistent. Thread t owns float4 lanes {j*512+t},
// j=0..3, of every row: it cp.async's exactly those 4x16B pieces into the
// ring slot and later reads exactly those back -> no cross-thread hazard,
// no __syncthreads in the pipeline. 6-stage ring = 5 rows ahead in flight.
__global__ __launch_bounds__(NTHR, 1) void dot_cp_kernel(const float* __restrict__ x,
                                                         float* __restrict__ out) {
    extern __shared__ __align__(128) unsigned char dsm[];
    const int t   = threadIdx.x;
    const int bid = blockIdx.x;
    const uint32_t smb = (uint32_t)__cvta_generic_to_shared(dsm);

    const int nrows = (ROWS - 1 - bid) / GRID + 1;   // 7 for bid<136 else 6

    // w chunk in registers (L2 hit).
    float4 w[4];
    const float4* __restrict__ w4 = reinterpret_cast<const float4*>(g_wtotal);
#pragma unroll
    for (int j = 0; j < 4; ++j) w[j] = w4[j * NTHR + t];

    const float* __restrict__ xb = x + (size_t)bid * COLS;

    // Prologue: issue 5 stages (commit a group each, empty beyond nrows).
#pragma unroll
    for (int p = 0; p < NST - 1; ++p) {
        if (p < nrows) {
            const float* src = xb + (size_t)p * GRID * COLS;
            const uint32_t dst = smb + p * STAGE_BYTES;
#pragma unroll
            for (int j = 0; j < 4; ++j)
                cp16(dst + (j * NTHR + t) * 16, src + (size_t)(j * NTHR + t) * 4);
        }
        CP_COMMIT();
    }

    float s[MAXK];
    int slot = 0, nslot = NST - 1;
    for (int k = 0; k < nrows; ++k) {
        CP_WAIT(NST - 2);    // oldest group (stage k) has landed

        const float4* xs = reinterpret_cast<const float4*>(dsm + slot * STAGE_BYTES);
        float4 a0 = xs[0 * NTHR + t];
        float4 a1 = xs[1 * NTHR + t];
        float4 a2 = xs[2 * NTHR + t];
        float4 a3 = xs[3 * NTHR + t];

        float p0 = 0.f, p1 = 0.f;
        p0 = fmaf(a0.x, w[0].x, p0); p0 = fmaf(a0.y, w[0].y, p0);
        p0 = fmaf(a0.z, w[0].z, p0); p0 = fmaf(a0.w, w[0].w, p0);
        p1 = fmaf(a1.x, w[1].x, p1); p1 = fmaf(a1.y, w[1].y, p1);
        p1 = fmaf(a1.z, w[1].z, p1); p1 = fmaf(a1.w, w[1].w, p1);
        p0 = fmaf(a2.x, w[2].x, p0); p0 = fmaf(a2.y, w[2].y, p0);
        p0 = fmaf(a2.z, w[2].z, p0); p0 = fmaf(a2.w, w[2].w, p0);
        p1 = fmaf(a3.x, w[3].x, p1); p1 = fmaf(a3.y, w[3].y, p1);
        p1 = fmaf(a3.z, w[3].z, p1); p1 = fmaf(a3.w, w[3].w, p1);
        s[k] = p0 + p1;

        // Refill: stage k+5 into the slot read at iteration k-1 (own chunks only).
        const int kn = k + NST - 1;
        if (kn < nrows) {
            const float* src = xb + (size_t)kn * GRID * COLS;
            const uint32_t dst = smb + nslot * STAGE_BYTES;
#pragma unroll
            for (int j = 0; j < 4; ++j)
                cp16(dst + (j * NTHR + t) * 16, src + (size_t)(j * NTHR + t) * 4);
        }
        CP_COMMIT();

        if (++slot == NST) slot = 0;
        if (++nslot == NST) nslot = 0;
    }
    CP_WAIT(0);

    // Deferred reductions: warp shuffles, then one combine.
#pragma unroll
    for (int o = 16; o > 0; o >>= 1) {
#pragma unroll
        for (int k = 0; k < MAXK; ++k)
            if (k < nrows) s[k] += __shfl_xor_sync(0xFFFFFFFFu, s[k], o);
    }

    __shared__ float red[MAXK][NTHR / 32];
    const int wid = t >> 5, lid = t & 31;
    if (lid == 0) {
#pragma unroll
        for (int k = 0; k < MAXK; ++k)
            if (k < nrows) red[k][wid] = s[k];
    }
    __syncthreads();

    if (t < nrows) {
        float v = 0.f;
#pragma unroll
        for (int w16 = 0; w16 < NTHR / 32; ++w16) v += red[t][w16];
        out[bid + t * GRID] = v * SCALE;
    }
}

extern "C" void kernel_launch(void* const* d_in, const int* in_sizes, int n_in,
                              void* d_out, int out_size) {
    const float* x     = (const float*)d_in[0];  // [1024, 8192] f32
    const float* wsums = (const float*)d_in[1];  // [32, 8192] f32
    float* out         = (float*)d_out;          // [1024, 1] f32

    cudaFuncSetAttribute(dot_cp_kernel,
                         cudaFuncAttributeMaxDynamicSharedMemorySize, DYN_SMEM);

    reduce_w_kernel<<<COLS4 / 32, 256>>>(wsums);
    dot_cp_kernel<<<GRID, NTHR, DYN_SMEM>>>(x, out);
}

// round 9
// speedup vs baseline: 1.2610x; 1.2316x over previous
#include <cuda_runtime.h>
#include <cstdint>

#define COLS 8192
#define COLS4 2048
#define ROWS 1024
#define SCALE 0.75f
#define HALF 4096             // floats per half-row

// Scratch (no allocation allowed). 32B-aligned for LDG.256.
__device__ __align__(32) float g_wtotal[COLS];

// LDG.256 + evict_last (x stream: L2-resident across graph replays).
__device__ __forceinline__ void ldg256_el(const float* p, float4& a, float4& b) {
    unsigned r0, r1, r2, r3, r4, r5, r6, r7;
    asm volatile("ld.global.nc.L2::evict_last.v8.b32 {%0,%1,%2,%3,%4,%5,%6,%7}, [%8];"
        : "=r"(r0), "=r"(r1), "=r"(r2), "=r"(r3),
          "=r"(r4), "=r"(r5), "=r"(r6), "=r"(r7)
        : "l"(p));
    a.x = __uint_as_float(r0); a.y = __uint_as_float(r1);
    a.z = __uint_as_float(r2); a.w = __uint_as_float(r3);
    b.x = __uint_as_float(r4); b.y = __uint_as_float(r5);
    b.z = __uint_as_float(r6); b.w = __uint_as_float(r7);
}
// Plain LDG.256 (w: L1-hot, 32 KB).
__device__ __forceinline__ void ldg256(const float* p, float4& a, float4& b) {
    unsigned r0, r1, r2, r3, r4, r5, r6, r7;
    asm volatile("ld.global.nc.v8.b32 {%0,%1,%2,%3,%4,%5,%6,%7}, [%8];"
        : "=r"(r0), "=r"(r1), "=r"(r2), "=r"(r3),
          "=r"(r4), "=r"(r5), "=r"(r6), "=r"(r7)
        : "l"(p));
    a.x = __uint_as_float(r0); a.y = __uint_as_float(r1);
    a.z = __uint_as_float(r2); a.w = __uint_as_float(r3);
    b.x = __uint_as_float(r4); b.y = __uint_as_float(r5);
    b.z = __uint_as_float(r6); b.w = __uint_as_float(r7);
}

// ---------------- Kernel 1: w_total[c] = sum_g wsums[g][c] ----------------
__global__ __launch_bounds__(256) void reduce_w_kernel(const float* __restrict__ wsums) {
    const int lcol  = threadIdx.x & 31;
    const int chunk = threadIdx.x >> 5;               // 0..7, 4 groups each
    const int c4    = blockIdx.x * 32 + lcol;

    const float4* __restrict__ w4 = reinterpret_cast<const float4*>(wsums);
    float4 s = make_float4(0.f, 0.f, 0.f, 0.f);
#pragma unroll
    for (int g = 0; g < 4; ++g) {
        float4 v = w4[(size_t)(chunk * 4 + g) * COLS4 + c4];
        s.x += v.x; s.y += v.y; s.z += v.z; s.w += v.w;
    }

    __shared__ float4 sm[8][32];
    sm[chunk][lcol] = s;
    __syncthreads();

    if (threadIdx.x < 32) {
        float4 r = make_float4(0.f, 0.f, 0.f, 0.f);
#pragma unroll
        for (int c = 0; c < 8; ++c) {
            float4 v = sm[c][threadIdx.x];
            r.x += v.x; r.y += v.y; r.z += v.z; r.w += v.w;
        }
        reinterpret_cast<float4*>(g_wtotal)[c4] = r;
    }
}

// ---------------- Kernel 2: warp-per-half-row long-loop matvec ----------------
// Grid 128 x 512 threads (16 warps). Warp wid owns half-row bid*16+wid:
// a 16-iteration stride loop (1 KB/warp/iter), #pragma unroll 4 so ptxas
// software-pipelines loads ahead of FMAs. No sync anywhere in the stream.
__global__ __launch_bounds__(512, 1) void dot_warp_kernel(const float* __restrict__ x,
                                                          float* __restrict__ out) {
    const int t   = threadIdx.x;
    const int wid = t >> 5;
    const int lid = t & 31;
    const int row  = blockIdx.x * 8 + (wid >> 1);
    const int half = wid & 1;

    const float* __restrict__ xr = x + (size_t)row * COLS + half * HALF + lid * 8;
    const float* __restrict__ wr = g_wtotal + half * HALF + lid * 8;

    float p0 = 0.f, p1 = 0.f, p2 = 0.f, p3 = 0.f;
#pragma unroll 4
    for (int i = 0; i < 16; ++i) {
        float4 a0, a1, b0, b1;
        ldg256_el(xr + i * 256, a0, a1);
        ldg256  (wr + i * 256, b0, b1);
        p0 = fmaf(a0.x, b0.x, p0); p1 = fmaf(a0.y, b0.y, p1);
        p2 = fmaf(a0.z, b0.z, p2); p3 = fmaf(a0.w, b0.w, p3);
        p0 = fmaf(a1.x, b1.x, p0); p1 = fmaf(a1.y, b1.y, p1);
        p2 = fmaf(a1.z, b1.z, p2); p3 = fmaf(a1.w, b1.w, p3);
    }
    float s = (p0 + p1) + (p2 + p3);

    // Warp reduce.
#pragma unroll
    for (int o = 16; o > 0; o >>= 1)
        s += __shfl_xor_sync(0xFFFFFFFFu, s, o);

    __shared__ float red[16];
    if (lid == 0) red[wid] = s;
    __syncthreads();

    if (t < 8)
        out[blockIdx.x * 8 + t] = SCALE * (red[2 * t] + red[2 * t + 1]);
}

extern "C" void kernel_launch(void* const* d_in, const int* in_sizes, int n_in,
                              void* d_out, int out_size) {
    const float* x     = (const float*)d_in[0];  // [1024, 8192] f32
    const float* wsums = (const float*)d_in[1];  // [32, 8192] f32
    float* out         = (float*)d_out;          // [1024, 1] f32

    reduce_w_kernel<<<COLS4 / 32, 256>>>(wsums);
    dot_warp_kernel<<<ROWS / 8, 512>>>(x, out);
}